// round 1
// baseline (speedup 1.0000x reference)
#include <cuda_runtime.h>

#define FULL 0xffffffffu

// 12-qubit real statevector QNN, one sample per warp, state register-resident.
// Index convention: global amplitude index b (12 bits), wire w lives at bit (11-w).
// b = (lane << 7) | r  : lane bits = wires 0..4, register bits = wires 5..11.
__global__ void __launch_bounds__(128, 2) qnn_65481071395397_kernel(
    const float* __restrict__ sb,      // (B, 12) encoding angles
    const float* __restrict__ params,  // (12,)   shared variational angles
    const float* __restrict__ hw,      // (12,)   head weights
    const float* __restrict__ hb,      // (1,)    head bias
    float* __restrict__ out,           // (B,)
    int B)
{
    const int lane   = threadIdx.x & 31;
    const int warp   = threadIdx.x >> 5;
    const int sample = blockIdx.x * (blockDim.x >> 5) + warp;
    if (sample >= B) return;   // warp-aligned guard (B % 4 CTA-warps handled)

    // ---- shared variational angles: cos/sin of theta/2 ----
    float cp[12], sp[12];
#pragma unroll
    for (int w = 0; w < 12; w++) {
        float s, c;
        __sincosf(0.5f * params[w], &s, &c);
        cp[w] = c; sp[w] = s;
    }

    // ---- encoding: build product state directly (== RY(x_w) applied to |0..0>) ----
    float v[128];
    {
        const float* row = sb + (long)sample * 12;
        // lane-wire factors (wires 0..4, lane bit (4-w))
        float lf = 1.0f;
#pragma unroll
        for (int w = 0; w < 5; w++) {
            float s, c;
            __sincosf(0.5f * row[w], &s, &c);
            lf *= ((lane >> (4 - w)) & 1) ? s : c;
        }
        // register-wire tensor tree (wires 11 down to 5 -> reg bits 0..6)
        v[0] = lf;
#pragma unroll
        for (int w = 11; w >= 5; w--) {
            float s, c;
            __sincosf(0.5f * row[w], &s, &c);
            const int size = 1 << (11 - w);
#pragma unroll
            for (int i = 0; i < size; i++) {
                v[i + size] = v[i] * s;
                v[i]        = v[i] * c;
            }
        }
    }

    const int  srcLane = lane ^ (lane >> 1);  // lane part of Gray permutation
    const bool l0      = (lane & 1) != 0;     // lane bit0 == wire 4 (boundary CNOT ctrl)

    // ---- 4 variational layers ----
#pragma unroll 1
    for (int layer = 0; layer < 4; layer++) {
        // (a) CNOT ladder == Gray permutation: new[d] = old[d ^ (d>>1)]
        // step 1: lane Gray (slot-wise pull, in-place safe)
#pragma unroll
        for (int r = 0; r < 128; r++)
            v[r] = __shfl_sync(FULL, v[r], srcLane);
        // step 2: boundary CNOT(wire4 -> wire5): conditional half-swap on reg bit 6
#pragma unroll
        for (int j = 0; j < 64; j++) {
            float a = v[j], b = v[j + 64];
            v[j]      = l0 ? b : a;
            v[j + 64] = l0 ? a : b;
        }
        // step 3: register Gray (compile-time permutation -> register renaming)
        {
            float nv[128];
#pragma unroll
            for (int r = 0; r < 128; r++) nv[r] = v[r ^ (r >> 1)];
#pragma unroll
            for (int r = 0; r < 128; r++) v[r] = nv[r];
        }

        // (b) RY on register wires 5..11 (reg bit 11-w): pure register butterflies
#pragma unroll
        for (int w = 5; w < 12; w++) {
            const float c = cp[w], s = sp[w];
            const int   m = 1 << (11 - w);
#pragma unroll
            for (int r = 0; r < 128; r++) {
                if (r & m) continue;
                float a0 = v[r], a1 = v[r | m];
                v[r]     = fmaf(-s, a1, c * a0);
                v[r | m] = fmaf( c, a1, s * a0);
            }
        }

        // (c) RY on lane wires 0..4 (lane bit 4-w): shfl.bfly butterflies
#pragma unroll
        for (int w = 0; w < 5; w++) {
            const float c  = cp[w], s = sp[w];
            const int   lm = 1 << (4 - w);
            const float k  = (lane & lm) ? s : -s;   // sign by which side of the pair we are
#pragma unroll
            for (int r = 0; r < 128; r++) {
                float p = __shfl_xor_sync(FULL, v[r], lm);
                v[r] = fmaf(k, p, c * v[r]);
            }
        }
    }

    // ---- readout: out = sum_b G[b] * v[b]^2 + hb,  G separable over wires ----
    float g_hi[8], g_lo[16];
    {
        float gl = 0.0f;
#pragma unroll
        for (int w = 0; w < 5; w++)
            gl += ((lane >> (4 - w)) & 1) ? -hw[w] : hw[w];
        g_hi[0] = gl;                       // wires 5..7 (r bits 6..4)
#pragma unroll
        for (int w = 7; w >= 5; w--) {
            const int size = 1 << (7 - w);
#pragma unroll
            for (int i = 0; i < size; i++) {
                g_hi[i + size] = g_hi[i] - hw[w];
                g_hi[i]        = g_hi[i] + hw[w];
            }
        }
        g_lo[0] = 0.0f;                     // wires 8..11 (r bits 3..0)
#pragma unroll
        for (int w = 11; w >= 8; w--) {
            const int size = 1 << (11 - w);
#pragma unroll
            for (int i = 0; i < size; i++) {
                g_lo[i + size] = g_lo[i] - hw[w];
                g_lo[i]        = g_lo[i] + hw[w];
            }
        }
    }

    float acc0 = 0.f, acc1 = 0.f, acc2 = 0.f, acc3 = 0.f;
#pragma unroll
    for (int r = 0; r < 128; r += 4) {
        acc0 = fmaf(v[r + 0] * (g_hi[(r + 0) >> 4] + g_lo[(r + 0) & 15]), v[r + 0], acc0);
        acc1 = fmaf(v[r + 1] * (g_hi[(r + 1) >> 4] + g_lo[(r + 1) & 15]), v[r + 1], acc1);
        acc2 = fmaf(v[r + 2] * (g_hi[(r + 2) >> 4] + g_lo[(r + 2) & 15]), v[r + 2], acc2);
        acc3 = fmaf(v[r + 3] * (g_hi[(r + 3) >> 4] + g_lo[(r + 3) & 15]), v[r + 3], acc3);
    }
    float acc = (acc0 + acc1) + (acc2 + acc3);

    // warp reduction
#pragma unroll
    for (int off = 16; off > 0; off >>= 1)
        acc += __shfl_xor_sync(FULL, acc, off);

    if (lane == 0)
        out[sample] = acc + hb[0];
}

extern "C" void kernel_launch(void* const* d_in, const int* in_sizes, int n_in,
                              void* d_out, int out_size) {
    const float* sb     = (const float*)d_in[0];
    const float* params = (const float*)d_in[1];
    const float* hw     = (const float*)d_in[2];
    const float* hb     = (const float*)d_in[3];
    float*       out    = (float*)d_out;

    const int B = in_sizes[0] / 12;
    const int warpsPerBlock = 4;  // 128 threads
    const int blocks = (B + warpsPerBlock - 1) / warpsPerBlock;
    qnn_65481071395397_kernel<<<blocks, 128>>>(sb, params, hw, hb, out, B);
}

// round 2
// speedup vs baseline: 1.1430x; 1.1430x over previous
#include <cuda_runtime.h>

#define FULL 0xffffffffu

// sigma_K(r) = K-fold application of 7-bit Gray map g(r) = r ^ (r>>1).
// GF(2)-linear, so all indices below fold to compile-time constants after
// template instantiation + full unroll -> v[] stays register-resident.
template <int K>
__device__ __forceinline__ int sig(int r) {
#pragma unroll
    for (int i = 0; i < K; i++) r = (r ^ (r >> 1)) & 127;
    return r;
}

// One variational layer. Mapping on entry: logical reg-index r lives in
// physical slot sig<K>(r). On exit: sig<K+1>(r).
template <int K>
__device__ __forceinline__ void do_layer(float (&v)[128],
                                         const float (&cp)[12],
                                         const float (&sp)[12],
                                         int srcLane, bool l0, int lane) {
    // (a1) lane part of the 12-bit Gray permutation: physical shuffle.
    //      Slot-independent, so the current slot mapping doesn't matter.
#pragma unroll
    for (int r = 0; r < 128; r++)
        v[r] = __shfl_sync(FULL, v[r], srcLane);

    // (a2) boundary CNOT (wire4 -> wire5): where logical lane bit0 is set,
    //      swap logical reg indices j <-> j|64. Slots via sig<K>.
#pragma unroll
    for (int j = 0; j < 64; j++) {
        const int a = sig<K>(j), b = sig<K>(j | 64);
        float x = v[a], y = v[b];
        v[a] = l0 ? y : x;
        v[b] = l0 ? x : y;
    }

    // (a3) reg part of Gray: pure relabel -> indices below use sig<K+1>.

    // (b) RY on register wires 5..11 (logical reg bit 11-w): register butterflies.
#pragma unroll
    for (int w = 5; w < 12; w++) {
        const float c = cp[w], s = sp[w];
        const int   m = 1 << (11 - w);
#pragma unroll
        for (int r = 0; r < 128; r++) {
            if (r & m) continue;
            const int s0 = sig<K + 1>(r), s1 = sig<K + 1>(r | m);
            float a0 = v[s0], a1 = v[s1];
            v[s0] = fmaf(-s, a1, c * a0);
            v[s1] = fmaf( c, a1, s * a0);
        }
    }

    // (c) RY on lane wires 0..4 (lane bit 4-w): shfl.bfly butterflies.
#pragma unroll
    for (int w = 0; w < 5; w++) {
        const float c  = cp[w], s = sp[w];
        const int   lm = 1 << (4 - w);
        const float k  = (lane & lm) ? s : -s;
#pragma unroll
        for (int r = 0; r < 128; r++) {
            float p = __shfl_xor_sync(FULL, v[r], lm);
            v[r] = fmaf(k, p, c * v[r]);
        }
    }
}

__global__ void __launch_bounds__(128, 2) qnn_65481071395397_kernel(
    const float* __restrict__ sb,      // (B, 12) encoding angles
    const float* __restrict__ params,  // (12,)
    const float* __restrict__ hw,      // (12,)
    const float* __restrict__ hb,      // (1,)
    float* __restrict__ out,           // (B,)
    int B)
{
    const int lane   = threadIdx.x & 31;
    const int warp   = threadIdx.x >> 5;
    const int sample = blockIdx.x * (blockDim.x >> 5) + warp;
    if (sample >= B) return;  // whole warps exit together

    // ---- shared variational angles ----
    float cp[12], sp[12];
#pragma unroll
    for (int w = 0; w < 12; w++) {
        float s, c;
        __sincosf(0.5f * params[w], &s, &c);
        cp[w] = c; sp[w] = s;
    }

    // ---- encoding: product state |RY(x_0)..RY(x_11)|0..0> ----
    float v[128];
    {
        const float* row = sb + (long)sample * 12;
        float lf = 1.0f;
#pragma unroll
        for (int w = 0; w < 5; w++) {
            float s, c;
            __sincosf(0.5f * row[w], &s, &c);
            lf *= ((lane >> (4 - w)) & 1) ? s : c;
        }
        v[0] = lf;
#pragma unroll
        for (int w = 11; w >= 5; w--) {
            float s, c;
            __sincosf(0.5f * row[w], &s, &c);
            const int size = 1 << (11 - w);
#pragma unroll
            for (int i = 0; i < size; i++) {
                v[i + size] = v[i] * s;
                v[i]        = v[i] * c;
            }
        }
    }

    const int  srcLane = lane ^ (lane >> 1);
    const bool l0      = (lane & 1) != 0;

    // ---- 4 variational layers (slot mapping composed at compile time) ----
    do_layer<0>(v, cp, sp, srcLane, l0, lane);
    do_layer<1>(v, cp, sp, srcLane, l0, lane);
    do_layer<2>(v, cp, sp, srcLane, l0, lane);
    do_layer<3>(v, cp, sp, srcLane, l0, lane);

    // ---- readout: sum_b G(b) * psi_b^2, G separable over wires ----
    float g_hi[8], g_lo[16];
    {
        float gl = 0.0f;
#pragma unroll
        for (int w = 0; w < 5; w++)
            gl += ((lane >> (4 - w)) & 1) ? -hw[w] : hw[w];
        g_hi[0] = gl;  // lane part + wires 5..7 (reg bits 6..4)
#pragma unroll
        for (int w = 7; w >= 5; w--) {
            const int size = 1 << (7 - w);
#pragma unroll
            for (int i = 0; i < size; i++) {
                g_hi[i + size] = g_hi[i] - hw[w];
                g_hi[i]        = g_hi[i] + hw[w];
            }
        }
        g_lo[0] = 0.0f;  // wires 8..11 (reg bits 3..0)
#pragma unroll
        for (int w = 11; w >= 8; w--) {
            const int size = 1 << (11 - w);
#pragma unroll
            for (int i = 0; i < size; i++) {
                g_lo[i + size] = g_lo[i] - hw[w];
                g_lo[i]        = g_lo[i] + hw[w];
            }
        }
    }

    float acc0 = 0.f, acc1 = 0.f, acc2 = 0.f, acc3 = 0.f;
#pragma unroll
    for (int r = 0; r < 128; r += 4) {
        // logical index r -> slot sig<4>(r); weights indexed by logical bits
        const int q0 = sig<4>(r + 0), q1 = sig<4>(r + 1),
                  q2 = sig<4>(r + 2), q3 = sig<4>(r + 3);
        acc0 = fmaf(v[q0] * (g_hi[(r + 0) >> 4] + g_lo[(r + 0) & 15]), v[q0], acc0);
        acc1 = fmaf(v[q1] * (g_hi[(r + 1) >> 4] + g_lo[(r + 1) & 15]), v[q1], acc1);
        acc2 = fmaf(v[q2] * (g_hi[(r + 2) >> 4] + g_lo[(r + 2) & 15]), v[q2], acc2);
        acc3 = fmaf(v[q3] * (g_hi[(r + 3) >> 4] + g_lo[(r + 3) & 15]), v[q3], acc3);
    }
    float acc = (acc0 + acc1) + (acc2 + acc3);

#pragma unroll
    for (int off = 16; off > 0; off >>= 1)
        acc += __shfl_xor_sync(FULL, acc, off);

    if (lane == 0)
        out[sample] = acc + hb[0];
}

extern "C" void kernel_launch(void* const* d_in, const int* in_sizes, int n_in,
                              void* d_out, int out_size) {
    const float* sb     = (const float*)d_in[0];
    const float* params = (const float*)d_in[1];
    const float* hw     = (const float*)d_in[2];
    const float* hb     = (const float*)d_in[3];
    float*       out    = (float*)d_out;

    const int B = in_sizes[0] / 12;
    const int blocks = (B + 3) / 4;  // 4 warps per CTA
    qnn_65481071395397_kernel<<<blocks, 128>>>(sb, params, hw, hb, out, B);
}

// round 3
// speedup vs baseline: 5.1854x; 4.5367x over previous
#include <cuda_runtime.h>

#define FULL 0xffffffffu

// Invertible GF(2)-linear 5-bit map with T(3)=16 (preimage of 16 has even
// parity). Used to swizzle smem addresses so BOTH the store phase and the
// Gray-permuted load phase are bank-conflict-free.
// Columns: T(1)=1, T(2)=17, T(4)=4, T(8)=8, T(16)=2.
__device__ __forceinline__ int T5(int x) {
    return (x & 13) ^ (((x >> 1) & 1) * 17) ^ (((x >> 4) & 1) * 2);
}

// One sample per CTA (128 threads). b = (warp<<10)|(lane<<5)|r.
// wire w lives at bit (11-w): wires 0-1 -> warp bits, 2-6 -> lane bits,
// 7-11 -> register bits. v[32] per thread.
__global__ void __launch_bounds__(128, 5) qnn_65481071395397_kernel(
    const float* __restrict__ sb,      // (B, 12)
    const float* __restrict__ params,  // (12,)
    const float* __restrict__ hw,      // (12,)
    const float* __restrict__ hb,      // (1,)
    float* __restrict__ out)           // (B,)
{
    __shared__ float s[4096];
    __shared__ float partial[4];

    const int tid  = threadIdx.x;
    const int lane = tid & 31;
    const int warp = tid >> 5;
    const int sample = blockIdx.x;

    // ---- encoding: product state from per-sample angles ----
    const float* row = sb + (long)sample * 12;
    float v[32];
    {
        float ec[12], es[12];
#pragma unroll
        for (int w = 0; w < 12; w++)
            __sincosf(0.5f * row[w], &es[w], &ec[w]);

        float lf = 1.0f;
        lf *= (warp & 2) ? es[0] : ec[0];              // wire0 = warp bit1
        lf *= (warp & 1) ? es[1] : ec[1];              // wire1 = warp bit0
#pragma unroll
        for (int w = 2; w <= 6; w++)                   // wire w = lane bit (6-w)
            lf *= ((lane >> (6 - w)) & 1) ? es[w] : ec[w];

        v[0] = lf;                                     // reg tree, wires 11..7
#pragma unroll
        for (int w = 11; w >= 7; w--) {
            const int size = 1 << (11 - w);
#pragma unroll
            for (int i = 0; i < size; i++) {
                v[i + size] = v[i] * es[w];
                v[i]        = v[i] * ec[w];
            }
        }
    }

    // ---- shared variational angles ----
    float cp[12], sp[12];
#pragma unroll
    for (int w = 0; w < 12; w++)
        __sincosf(0.5f * params[w], &sp[w], &cp[w]);

    // 4x4 warp-combine row: M[W][W'] = RY0[b1][b1'] * RY1[b0][b0']
    // (RY: [0][0]=c, [0][1]=-s, [1][0]=s, [1][1]=c)
    float m0, m1, m2, m3;
    {
        const int b1 = (warp >> 1) & 1, b0 = warp & 1;
        const float r1_0 = b1 ? sp[0] : cp[0];
        const float r1_1 = b1 ? cp[0] : -sp[0];
        const float r0_0 = b0 ? sp[1] : cp[1];
        const float r0_1 = b0 ? cp[1] : -sp[1];
        m0 = r1_0 * r0_0;   // W'=0
        m1 = r1_0 * r0_1;   // W'=1
        m2 = r1_1 * r0_0;   // W'=2
        m3 = r1_1 * r0_1;   // W'=3
    }

    // store base: addr = (warp<<10)|(lane<<5)|(r ^ T5(lane))
    const int stbase = (warp << 10) | (lane << 5) | T5(lane);

    // load bases: for each partner warp W', address of smem slot holding
    // psi_pre[g(b')] where b' = (W'<<10)|(lane<<5)|r, g(t)=t^(t>>1).
    // Inner loop XORs gray(r)=r^(r>>1) into the low 5 bits.
    int base[4];
    {
        const int gl = lane ^ (lane >> 1);             // Gray5(lane)
#pragma unroll
        for (int Wp = 0; Wp < 4; Wp++) {
            const int hi5   = gl ^ ((Wp & 1) << 4);    // bits 5..9 of g(b')
            const int bit10 = (Wp & 1) ^ (Wp >> 1);
            const int bit11 = Wp >> 1;
            const int low5  = ((lane & 1) << 4) ^ T5(hi5);
            base[Wp] = (bit11 << 11) | (bit10 << 10) | (hi5 << 5) | low5;
        }
    }

    // ---- 4 variational layers ----
#pragma unroll 1
    for (int layer = 0; layer < 4; layer++) {
        __syncthreads();
#pragma unroll
        for (int r = 0; r < 32; r++)
            s[stbase ^ r] = v[r];
        __syncthreads();

        // Gray permutation (all 11 CNOTs) + both warp-wire RYs, fused:
        // v[r] = sum_W' M[W][W'] * psi_pre[g((W'<<10)|(lane<<5)|r)]
#pragma unroll
        for (int r = 0; r < 32; r++) {
            const int gr = r ^ (r >> 1);
            const float a0 = s[base[0] ^ gr];
            const float a1 = s[base[1] ^ gr];
            const float a2 = s[base[2] ^ gr];
            const float a3 = s[base[3] ^ gr];
            v[r] = fmaf(m3, a3, fmaf(m2, a2, fmaf(m1, a1, m0 * a0)));
        }

        // RY on register wires 7..11 (reg bit 11-w)
#pragma unroll
        for (int w = 7; w < 12; w++) {
            const float c = cp[w], sv = sp[w];
            const int mbit = 1 << (11 - w);
#pragma unroll
            for (int r = 0; r < 32; r++) {
                if (r & mbit) continue;
                const float a0 = v[r], a1 = v[r | mbit];
                v[r]        = fmaf(-sv, a1, c * a0);
                v[r | mbit] = fmaf( c, a1, sv * a0);
            }
        }

        // RY on lane wires 2..6 (lane bit 6-w) via shfl.bfly
#pragma unroll
        for (int w = 2; w < 7; w++) {
            const float c = cp[w], sv = sp[w];
            const int lm = 1 << (6 - w);
            const float k = (lane & lm) ? sv : -sv;
#pragma unroll
            for (int r = 0; r < 32; r++) {
                const float p = __shfl_xor_sync(FULL, v[r], lm);
                v[r] = fmaf(k, p, c * v[r]);
            }
        }
    }

    // ---- readout: sum_b G(b) * psi_b^2, G additive-separable over wires ----
    float gwl = 0.0f;
    gwl += (warp & 2) ? -hw[0] : hw[0];
    gwl += (warp & 1) ? -hw[1] : hw[1];
#pragma unroll
    for (int w = 2; w <= 6; w++)
        gwl += ((lane >> (6 - w)) & 1) ? -hw[w] : hw[w];
    const float h7 = hw[7], h8 = hw[8], h9 = hw[9], h10 = hw[10], h11 = hw[11];

    float acc = 0.0f;
#pragma unroll
    for (int r = 0; r < 32; r++) {
        const float g = gwl
            + ((r & 16) ? -h7  : h7)
            + ((r &  8) ? -h8  : h8)
            + ((r &  4) ? -h9  : h9)
            + ((r &  2) ? -h10 : h10)
            + ((r &  1) ? -h11 : h11);
        acc = fmaf(v[r] * g, v[r], acc);
    }

#pragma unroll
    for (int off = 16; off > 0; off >>= 1)
        acc += __shfl_xor_sync(FULL, acc, off);

    if (lane == 0) partial[warp] = acc;
    __syncthreads();
    if (tid == 0)
        out[sample] = (partial[0] + partial[1]) + (partial[2] + partial[3]) + hb[0];
}

extern "C" void kernel_launch(void* const* d_in, const int* in_sizes, int n_in,
                              void* d_out, int out_size) {
    const float* sb     = (const float*)d_in[0];
    const float* params = (const float*)d_in[1];
    const float* hw     = (const float*)d_in[2];
    const float* hb     = (const float*)d_in[3];
    float*       out    = (float*)d_out;

    const int B = in_sizes[0] / 12;   // 8192
    qnn_65481071395397_kernel<<<B, 128>>>(sb, params, hw, hb, out);
}